// round 14
// baseline (speedup 1.0000x reference)
#include <cuda_runtime.h>
#include <math.h>
#include <stdint.h>

#define BSZ 512
#define DSZ 256
#define EPSF 1e-8f
#define MARGINF 0.3f
#define UWF 0.05f

// ---------------------------------------------------------------------------
// scratch (__device__ globals; no cudaMalloc allowed)
// Zero is the identity for both atomics (neg side stored complemented) and
// integer max is idempotent/order-independent -> graph-replay deterministic.
// ---------------------------------------------------------------------------
__device__ unsigned long long g_posbest[BSZ];    // packed max (0 = none)
__device__ unsigned long long g_negbest[BSZ];    // ~packed min (0 = none)
__device__ float g_bl[128], g_bv[128], g_bu[128];
__device__ unsigned int g_ctr = 0;               // wraps via atomicInc(.,127)

// packed f32x2 FMA: d = a*b + d (lane-wise IEEE fma)
#define FMA2(d, a, b) \
    asm("fma.rn.f32x2 %0, %1, %2, %0;" : "+l"(d) : "l"(a), "l"(b))

__device__ __forceinline__ uint32_t smem_u32(const void* p) {
    uint32_t r;
    asm("{ .reg .u64 t; cvta.to.shared.u64 t, %1; cvt.u32.u64 %0, t; }"
        : "=r"(r) : "l"(p));
    return r;
}

// ---------------------------------------------------------------------------
// K1: SYMMETRIC upper-triangle mining, 32(i) x 32(j) tiles (J >= I),
//     136 blocks, 128 threads, thread-tile 2i x 4j.
//     TWO 128-d chunks (4 syncthreads total instead of 16), high-MLP staging.
//     Row mining (anchors=i) AND column mining (anchors=j) via atomicMax.
// ---------------------------------------------------------------------------
__global__ __launch_bounds__(128) void k_dist_mine(const float* __restrict__ E,
                                                   const int*   __restrict__ L) {
    __shared__ __align__(16) float As[128][36];   // [d_local][i]
    __shared__ __align__(16) float Bs[128][36];   // [d_local][j]
    __shared__ float sni[32], snj[32];
    __shared__ int   sli[32], slj[32];

    const int t = threadIdx.x;

    // map bid -> (I, J), J >= I, 16x16 tile grid upper triangle (136 tiles)
    int I = 0, rem = blockIdx.x;
    while (rem >= 16 - I) { rem -= 16 - I; I++; }
    const int J = I + rem;
    const int i0 = I * 32;
    const int j0 = J * 32;

    const int tx = t & 7;         // j-quad (0..7)
    const int ty = t >> 3;        // i-pair (0..15)
    const int lane = t & 31;
    const float4* E4 = (const float4*)E;

    // loaders: 32 rows x 4 threads/row, 8 float4 per thread per chunk
    const int ar = t >> 2, aq = t & 3;

    if (t < 32) { sli[t] = L[i0 + t]; slj[t] = L[j0 + t]; }

    // acc[0]=i0x{j0,j1} acc[1]=i0x{j2,j3} acc[2]=i1x{j0,j1} acc[3]=i1x{j2,j3}
    uint64_t acc[4] = {0, 0, 0, 0};
    float nA = 0.f, nB = 0.f;

    const uint32_t as_base = smem_u32(&As[0][2 * ty]);
    const uint32_t bs_base = smem_u32(&Bs[0][4 * tx]);

    float4 pa[8], pb[8];
#pragma unroll
    for (int k = 0; k < 8; k++) {        // chunk 0: d 0..127 (f4 slots 0..31)
        pa[k] = E4[(i0 + ar) * 64 + aq + 4 * k];
        pb[k] = E4[(j0 + ar) * 64 + aq + 4 * k];
    }

#pragma unroll 1
    for (int ch = 0; ch < 2; ch++) {
        // inline norms from prefetched registers
#pragma unroll
        for (int k = 0; k < 8; k++) {
            nA = fmaf(pa[k].x, pa[k].x, nA); nA = fmaf(pa[k].y, pa[k].y, nA);
            nA = fmaf(pa[k].z, pa[k].z, nA); nA = fmaf(pa[k].w, pa[k].w, nA);
            nB = fmaf(pb[k].x, pb[k].x, nB); nB = fmaf(pb[k].y, pb[k].y, nB);
            nB = fmaf(pb[k].z, pb[k].z, nB); nB = fmaf(pb[k].w, pb[k].w, nB);
        }
        // stage transposed
#pragma unroll
        for (int k = 0; k < 8; k++) {
            int q = aq + 4 * k;          // f4 slot within chunk (0..31)
            As[q * 4 + 0][ar] = pa[k].x;
            As[q * 4 + 1][ar] = pa[k].y;
            As[q * 4 + 2][ar] = pa[k].z;
            As[q * 4 + 3][ar] = pa[k].w;
            Bs[q * 4 + 0][ar] = pb[k].x;
            Bs[q * 4 + 1][ar] = pb[k].y;
            Bs[q * 4 + 2][ar] = pb[k].z;
            Bs[q * 4 + 3][ar] = pb[k].w;
        }
        __syncthreads();

        if (ch == 0) {                    // prefetch chunk 1 under compute
#pragma unroll
            for (int k = 0; k < 8; k++) {
                pa[k] = E4[(i0 + ar) * 64 + 32 + aq + 4 * k];
                pb[k] = E4[(j0 + ar) * 64 + 32 + aq + 4 * k];
            }
        }

#pragma unroll 4
        for (int d = 0; d < 128; d++) {
            uint64_t a01;
            asm("ld.shared.b64 %0, [%1];"
                : "=l"(a01) : "r"(as_base + d * (36 * 4)));
            uint32_t b0, b1, b2, b3;
            asm("ld.shared.v4.b32 {%0, %1, %2, %3}, [%4];"
                : "=r"(b0), "=r"(b1), "=r"(b2), "=r"(b3)
                : "r"(bs_base + d * (36 * 4)));
            uint64_t bb0, bb1, bb2, bb3;
            asm("mov.b64 %0, {%1, %1};" : "=l"(bb0) : "r"(b0));
            asm("mov.b64 %0, {%1, %1};" : "=l"(bb1) : "r"(b1));
            asm("mov.b64 %0, {%1, %1};" : "=l"(bb2) : "r"(b2));
            asm("mov.b64 %0, {%1, %1};" : "=l"(bb3) : "r"(b3));
            FMA2(acc[0], a01, bb0);
            FMA2(acc[1], a01, bb1);
            FMA2(acc[2], a01, bb2);
            FMA2(acc[3], a01, bb3);
        }
        if (ch == 0) __syncthreads();
    }

    // publish row norms (4 loader threads per row)
    nA += __shfl_xor_sync(0xffffffffu, nA, 1);
    nA += __shfl_xor_sync(0xffffffffu, nA, 2);
    nB += __shfl_xor_sync(0xffffffffu, nB, 1);
    nB += __shfl_xor_sync(0xffffffffu, nB, 2);
    __syncthreads();                      // mainloop fully done before reuse
    if (aq == 0) { sni[ar] = nA; snj[ar] = nB; }
    __syncthreads();

    // unpack dots dt[r][c]: r = i within pair, c = j within quad
    float dt[2][4];
    {
        uint32_t lo, hi;
        asm("mov.b64 {%0, %1}, %2;" : "=r"(lo), "=r"(hi) : "l"(acc[0]));
        dt[0][0] = __uint_as_float(lo); dt[1][0] = __uint_as_float(hi);
        asm("mov.b64 {%0, %1}, %2;" : "=r"(lo), "=r"(hi) : "l"(acc[1]));
        dt[0][1] = __uint_as_float(lo); dt[1][1] = __uint_as_float(hi);
        asm("mov.b64 {%0, %1}, %2;" : "=r"(lo), "=r"(hi) : "l"(acc[2]));
        dt[0][2] = __uint_as_float(lo); dt[1][2] = __uint_as_float(hi);
        asm("mov.b64 {%0, %1}, %2;" : "=r"(lo), "=r"(hi) : "l"(acc[3]));
        dt[0][3] = __uint_as_float(lo); dt[1][3] = __uint_as_float(hi);
    }
    // NOTE: acc layout: low half = i row 2ty, high = 2ty+1; acc[c] covers
    // j = 4tx + c with the pairing used above:
    //   acc[0]={j0,j1} low/high split across FMA2 lanes -> we packed
    //   (a01 = rows pair) x (bb_c = dup of col c), so lo=row0, hi=row1. OK.

    float njv[4]; int ljv[4];
#pragma unroll
    for (int c = 0; c < 4; c++) { njv[c] = snj[4 * tx + c]; ljv[c] = slj[4 * tx + c]; }
    int liv[2]; float niv[2];
#pragma unroll
    for (int r = 0; r < 2; r++) { liv[r] = sli[2 * ty + r]; niv[r] = sni[2 * ty + r]; }

    float dval[2][4];
#pragma unroll
    for (int r = 0; r < 2; r++)
#pragma unroll
        for (int c = 0; c < 4; c++)
            dval[r][c] = sqrtf(fmaxf(niv[r] + njv[c] - 2.f * dt[r][c], 0.f)) + EPSF;

    // ---- row mining: anchor = i, candidates = this tile's j's ----
#pragma unroll
    for (int r = 0; r < 2; r++) {
        const int gi = i0 + 2 * ty + r;
        const int la = liv[r];
        unsigned long long bp = 0ull, bn = ~0ull;
#pragma unroll
        for (int c = 0; c < 4; c++) {
            const int jg = j0 + 4 * tx + c;
            unsigned long long enc =
                ((unsigned long long)__float_as_uint(dval[r][c]) << 32);
            if (ljv[c] == la && jg != gi) {
                unsigned long long cnd = enc | (0xFFFFFFFFu - (unsigned)jg);
                if (cnd > bp) bp = cnd;
            }
            if (ljv[c] != la) {
                unsigned long long cnd = enc | (unsigned)jg;
                if (cnd < bn) bn = cnd;
            }
        }
#pragma unroll
        for (int off = 4; off; off >>= 1) {
            unsigned long long o = __shfl_down_sync(0xffffffffu, bp, off, 8);
            if (o > bp) bp = o;
            o = __shfl_down_sync(0xffffffffu, bn, off, 8);
            if (o < bn) bn = o;
        }
        if (tx == 0) {
            if (bp) atomicMax(&g_posbest[gi], bp);
            if (bn != ~0ull) atomicMax(&g_negbest[gi], ~bn);
        }
    }

    // ---- column mining: anchor = j, candidates = this tile's i's ----
#pragma unroll
    for (int c = 0; c < 4; c++) {
        const int jg = j0 + 4 * tx + c;
        const int lj = ljv[c];
        unsigned long long bp = 0ull, bn = ~0ull;
#pragma unroll
        for (int r = 0; r < 2; r++) {
            const int gi = i0 + 2 * ty + r;
            unsigned long long enc =
                ((unsigned long long)__float_as_uint(dval[r][c]) << 32);
            if (liv[r] == lj && gi != jg) {
                unsigned long long cnd = enc | (0xFFFFFFFFu - (unsigned)gi);
                if (cnd > bp) bp = cnd;
            }
            if (liv[r] != lj) {
                unsigned long long cnd = enc | (unsigned)gi;
                if (cnd < bn) bn = cnd;
            }
        }
        // combine across the 4 ty values in this warp (lanes stride 8)
#pragma unroll
        for (int off = 16; off >= 8; off >>= 1) {
            unsigned long long o = __shfl_down_sync(0xffffffffu, bp, off, 32);
            if (o > bp) bp = o;
            o = __shfl_down_sync(0xffffffffu, bn, off, 32);
            if (o < bn) bn = o;
        }
        if (lane < 8) {
            if (bp) atomicMax(&g_posbest[jg], bp);
            if (bn != ~0ull) atomicMax(&g_negbest[jg], ~bn);
        }
    }
}

// ---------------------------------------------------------------------------
// K2: read final candidates, dist_unc at selected pairs, loss, last-block
//     finish. grid 128 x 4 anchors, 256 threads.  [round-12 proven config]
// ---------------------------------------------------------------------------
__global__ __launch_bounds__(256) void k_finalize(const float* __restrict__ E,
                                                  const float* __restrict__ U,
                                                  float* __restrict__ out) {
    const int t = threadIdx.x;
    const int bid = blockIdx.x;
    const int i0 = bid * 4;
    const int w = t >> 5, lane = t & 31;
    const float4* E4 = (const float4*)E;
    const float4* U4 = (const float4*)U;

    __shared__ float s_d[8];
    __shared__ int   s_v[8];
    __shared__ float s_w[8];
    __shared__ float s_us[4];
    __shared__ float s_al[4], s_av[4];
    __shared__ int   s_islast;
    __shared__ float s_red[12];

    const int a = w >> 1, side = w & 1;
    const int ia = i0 + a;

    // prefetch anchor rows (independent of candidates)
    float4 ua = U4[ia * 64 + 2 * lane];
    float4 ub = U4[ia * 64 + 2 * lane + 1];
    float4 ea = E4[ia * 64 + 2 * lane];
    float4 eb = E4[ia * 64 + 2 * lane + 1];

    // candidate (lane 0 loads, broadcast)
    unsigned long long praw = 0ull;
    if (lane == 0) praw = side ? g_negbest[ia] : g_posbest[ia];
    praw = __shfl_sync(0xffffffffu, praw, 0);
    const bool have = (praw != 0ull);
    const unsigned long long p = side ? ~praw : praw;
    const float dval = __uint_as_float((uint32_t)(p >> 32));
    const int jx = have ? (side ? (int)(uint32_t)p
                                : (int)(0xFFFFFFFFu - (uint32_t)p))
                        : 0;

    // clip u (NaN -> 1e-6 via fmaxf semantics, Inf -> 1)
    ua.x = fminf(fmaxf(ua.x, 1e-6f), 1.f); ua.y = fminf(fmaxf(ua.y, 1e-6f), 1.f);
    ua.z = fminf(fmaxf(ua.z, 1e-6f), 1.f); ua.w = fminf(fmaxf(ua.w, 1e-6f), 1.f);
    ub.x = fminf(fmaxf(ub.x, 1e-6f), 1.f); ub.y = fminf(fmaxf(ub.y, 1e-6f), 1.f);
    ub.z = fminf(fmaxf(ub.z, 1e-6f), 1.f); ub.w = fminf(fmaxf(ub.w, 1e-6f), 1.f);
    float us = ((ua.x + ua.y) + (ua.z + ua.w)) + ((ub.x + ub.y) + (ub.z + ub.w));

    // W = sum_d u_ia^2 (e_ia - e_jx)^2
    {
        float4 ja = E4[jx * 64 + 2 * lane];
        float4 jb = E4[jx * 64 + 2 * lane + 1];
        float W = 0.f, df;
        df = ea.x - ja.x; W = fmaf(ua.x * ua.x, df * df, W);
        df = ea.y - ja.y; W = fmaf(ua.y * ua.y, df * df, W);
        df = ea.z - ja.z; W = fmaf(ua.z * ua.z, df * df, W);
        df = ea.w - ja.w; W = fmaf(ua.w * ua.w, df * df, W);
        df = eb.x - jb.x; W = fmaf(ub.x * ub.x, df * df, W);
        df = eb.y - jb.y; W = fmaf(ub.y * ub.y, df * df, W);
        df = eb.z - jb.z; W = fmaf(ub.z * ub.z, df * df, W);
        df = eb.w - jb.w; W = fmaf(ub.w * ub.w, df * df, W);
#pragma unroll
        for (int off = 16; off; off >>= 1) {
            W  += __shfl_down_sync(0xffffffffu, W, off);
            us += __shfl_down_sync(0xffffffffu, us, off);
        }
        if (lane == 0) {
            s_w[w] = W;
            s_d[w] = dval;
            s_v[w] = have ? 1 : 0;
            if (side == 0) s_us[a] = us;
        }
    }
    __syncthreads();

    // per-anchor loss
    if (t < 4) {
        const int q = t;
        float dp = s_d[2 * q], dn = s_d[2 * q + 1];
        bool valid = s_v[2 * q] && s_v[2 * q + 1];
        float wp = s_w[2 * q], wn = s_w[2 * q + 1];
        float up2 = wp / (dp * dp) + EPSF;
        float un2 = wn / (dn * dn) + EPSF;
        float sig = sqrtf(up2 + un2 + EPSF);
        float me = MARGINF + UWF * sig;
        float z = (dp - dn + me) / sig;
        float sp = fmaxf(z, 0.f) + log1pf(expf(-fabsf(z)));
        s_al[q] = valid ? sig * sp : 0.f;
        s_av[q] = valid ? 1.f : 0.f;
    }
    __syncthreads();

    if (t == 0) {
        g_bl[bid] = (s_al[0] + s_al[1]) + (s_al[2] + s_al[3]);
        g_bv[bid] = (s_av[0] + s_av[1]) + (s_av[2] + s_av[3]);
        g_bu[bid] = (s_us[0] + s_us[1]) + (s_us[2] + s_us[3]);
        __threadfence();
        s_islast = (atomicInc(&g_ctr, 127) == 127) ? 1 : 0;
    }
    __syncthreads();

    if (s_islast) {
        __threadfence();
        float l = 0.f, v = 0.f, u = 0.f;
        if (t < 128) {
            l = *(volatile float*)&g_bl[t];
            v = *(volatile float*)&g_bv[t];
            u = *(volatile float*)&g_bu[t];
        }
#pragma unroll
        for (int off = 16; off; off >>= 1) {
            l += __shfl_down_sync(0xffffffffu, l, off);
            v += __shfl_down_sync(0xffffffffu, v, off);
            u += __shfl_down_sync(0xffffffffu, u, off);
        }
        if (lane == 0 && w < 4) {
            s_red[w] = l; s_red[4 + w] = v; s_red[8 + w] = u;
        }
        __syncthreads();
        if (t == 0) {
            float L = (s_red[0] + s_red[1]) + (s_red[2] + s_red[3]);
            float V = (s_red[4] + s_red[5]) + (s_red[6] + s_red[7]);
            float Uu = (s_red[8] + s_red[9]) + (s_red[10] + s_red[11]);
            float total = L / fmaxf(V, 1.0f) + UWF * (Uu / (float)(BSZ * DSZ));
            if (isnan(total) || isinf(total)) total = 0.f;
            out[0] = total;
        }
    }
}

// ---------------------------------------------------------------------------
extern "C" void kernel_launch(void* const* d_in, const int* in_sizes, int n_in,
                              void* d_out, int out_size) {
    const float* E = (const float*)d_in[0];
    const float* U = (const float*)d_in[1];
    const int*   L = (const int*)d_in[2];
    float* out = (float*)d_out;

    k_dist_mine<<<136, 128>>>(E, L);
    k_finalize<<<128, 256>>>(E, U, out);
}

// round 15
// speedup vs baseline: 1.0832x; 1.0832x over previous
#include <cuda_runtime.h>
#include <math.h>
#include <stdint.h>

#define BSZ 512
#define DSZ 256
#define EPSF 1e-8f
#define MARGINF 0.3f
#define UWF 0.05f

// ---------------------------------------------------------------------------
// scratch (__device__ globals; no cudaMalloc allowed)
// Zero is the identity for both atomics (neg side stored complemented) and
// integer max is idempotent/order-independent -> graph-replay deterministic.
// ---------------------------------------------------------------------------
__device__ unsigned long long g_posbest[BSZ];    // packed max (0 = none)
__device__ unsigned long long g_negbest[BSZ];    // ~packed min (0 = none)
__device__ float g_bl[128], g_bv[128], g_bu[128];
__device__ unsigned int g_ctr = 0;               // wraps via atomicInc(.,127)

// packed f32x2 FMA: d = a*b + d (lane-wise IEEE fma)
#define FMA2(d, a, b) \
    asm("fma.rn.f32x2 %0, %1, %2, %0;" : "+l"(d) : "l"(a), "l"(b))

__device__ __forceinline__ uint32_t smem_u32(const void* p) {
    uint32_t r;
    asm("{ .reg .u64 t; cvta.to.shared.u64 t, %1; cvt.u32.u64 %0, t; }"
        : "=r"(r) : "l"(p));
    return r;
}

// ---------------------------------------------------------------------------
// K1: 64(i) x 32(j) distance tiles, 256 threads, thread-tile 2i x 4j,
//     narrow-B loads (v4.b32 + register dup). FOUR 64-d chunks
//     (8 syncthreads instead of 16), prefetch 24 regs (no spill).
//     grid (16 j-tiles, 8 i-rows) = 128 blocks.  [R12 + chunk interpolation]
// ---------------------------------------------------------------------------
__global__ __launch_bounds__(256) void k_dist_mine(const float* __restrict__ E,
                                                   const int*   __restrict__ L) {
    __shared__ __align__(16) float As[64][68];   // [d_local][i] (64+pad)
    __shared__ __align__(16) float Bs[64][36];   // [d_local][j] (32+pad)
    __shared__ float sni[64], snj[32];
    __shared__ int   sli[64], slj[32];

    const int t = threadIdx.x;
    const int i0 = blockIdx.y * 64;
    const int j0 = blockIdx.x * 32;
    const int tx = t & 7;         // j-quad (0..7)
    const int ty = t >> 3;        // i-pair (0..31)
    const float4* E4 = (const float4*)E;

    // loader lanes
    const int ar = t >> 2, aq = t & 3;   // A: 64 rows x 4 threads, 4 f4/chunk
    const int br = t >> 3, bq = t & 7;   // B: 32 rows x 8 threads, 2 f4/chunk

    if (t < 64) sli[t] = L[i0 + t];
    if (t < 32) slj[t] = L[j0 + t];

    // acc[c] = i rows (2ty, 2ty+1) x j col (4tx+c)
    uint64_t acc[4] = {0, 0, 0, 0};
    float nA = 0.f, nB = 0.f;

    const uint32_t as_base = smem_u32(&As[0][2 * ty]);
    const uint32_t bs_base = smem_u32(&Bs[0][4 * tx]);

    float4 pa[4], pb[2];
#pragma unroll
    for (int k = 0; k < 4; k++) pa[k] = E4[(i0 + ar) * 64 + aq + 4 * k];
#pragma unroll
    for (int k = 0; k < 2; k++) pb[k] = E4[(j0 + br) * 64 + bq + 8 * k];

#pragma unroll 1
    for (int ch = 0; ch < 4; ch++) {
        // inline norm accumulation from prefetched registers
#pragma unroll
        for (int k = 0; k < 4; k++) {
            nA = fmaf(pa[k].x, pa[k].x, nA); nA = fmaf(pa[k].y, pa[k].y, nA);
            nA = fmaf(pa[k].z, pa[k].z, nA); nA = fmaf(pa[k].w, pa[k].w, nA);
        }
#pragma unroll
        for (int k = 0; k < 2; k++) {
            nB = fmaf(pb[k].x, pb[k].x, nB); nB = fmaf(pb[k].y, pb[k].y, nB);
            nB = fmaf(pb[k].z, pb[k].z, nB); nB = fmaf(pb[k].w, pb[k].w, nB);
        }

        // stage (transpose) into smem
#pragma unroll
        for (int k = 0; k < 4; k++) {
            int q = aq + 4 * k;           // f4 slot within chunk (0..15)
            As[q * 4 + 0][ar] = pa[k].x;
            As[q * 4 + 1][ar] = pa[k].y;
            As[q * 4 + 2][ar] = pa[k].z;
            As[q * 4 + 3][ar] = pa[k].w;
        }
#pragma unroll
        for (int k = 0; k < 2; k++) {
            int q = bq + 8 * k;
            Bs[q * 4 + 0][br] = pb[k].x;
            Bs[q * 4 + 1][br] = pb[k].y;
            Bs[q * 4 + 2][br] = pb[k].z;
            Bs[q * 4 + 3][br] = pb[k].w;
        }
        __syncthreads();

        if (ch < 3) {                     // prefetch next 64-d chunk
#pragma unroll
            for (int k = 0; k < 4; k++)
                pa[k] = E4[(i0 + ar) * 64 + (ch + 1) * 16 + aq + 4 * k];
#pragma unroll
            for (int k = 0; k < 2; k++)
                pb[k] = E4[(j0 + br) * 64 + (ch + 1) * 16 + bq + 8 * k];
        }

#pragma unroll
        for (int d = 0; d < 64; d++) {
            uint64_t a01;
            asm("ld.shared.b64 %0, [%1];"
                : "=l"(a01) : "r"(as_base + d * (68 * 4)));
            uint32_t b0, b1, b2, b3;
            asm("ld.shared.v4.b32 {%0, %1, %2, %3}, [%4];"
                : "=r"(b0), "=r"(b1), "=r"(b2), "=r"(b3)
                : "r"(bs_base + d * (36 * 4)));
            uint64_t bb0, bb1, bb2, bb3;
            asm("mov.b64 %0, {%1, %1};" : "=l"(bb0) : "r"(b0));
            asm("mov.b64 %0, {%1, %1};" : "=l"(bb1) : "r"(b1));
            asm("mov.b64 %0, {%1, %1};" : "=l"(bb2) : "r"(b2));
            asm("mov.b64 %0, {%1, %1};" : "=l"(bb3) : "r"(b3));
            FMA2(acc[0], a01, bb0);
            FMA2(acc[1], a01, bb1);
            FMA2(acc[2], a01, bb2);
            FMA2(acc[3], a01, bb3);
        }
        __syncthreads();
    }

    // publish row norms
    nA += __shfl_xor_sync(0xffffffffu, nA, 1);
    nA += __shfl_xor_sync(0xffffffffu, nA, 2);
    if (aq == 0) sni[ar] = nA;
    nB += __shfl_xor_sync(0xffffffffu, nB, 1);
    nB += __shfl_xor_sync(0xffffffffu, nB, 2);
    nB += __shfl_xor_sync(0xffffffffu, nB, 4);
    if (bq == 0) snj[br] = nB;
    __syncthreads();

    // unpack dots: dt[r][c], r = i within pair, c = j within quad
    float dt[2][4];
#pragma unroll
    for (int c = 0; c < 4; c++) {
        uint32_t lo, hi;
        asm("mov.b64 {%0, %1}, %2;" : "=r"(lo), "=r"(hi) : "l"(acc[c]));
        dt[0][c] = __uint_as_float(lo);
        dt[1][c] = __uint_as_float(hi);
    }

    float njv[4]; int ljv[4];
#pragma unroll
    for (int c = 0; c < 4; c++) { njv[c] = snj[4 * tx + c]; ljv[c] = slj[4 * tx + c]; }

#pragma unroll
    for (int r = 0; r < 2; r++) {
        const int gi = i0 + 2 * ty + r;
        const int la = sli[2 * ty + r];
        const float nir = sni[2 * ty + r];

        unsigned long long bp = 0ull;   // pos: max dist, same label, j!=i; tie -> low j
        unsigned long long bn = ~0ull;  // neg: min dist, diff label; tie -> low j
#pragma unroll
        for (int c = 0; c < 4; c++) {
            const int jg = j0 + 4 * tx + c;
            float dist = sqrtf(fmaxf(nir + njv[c] - 2.f * dt[r][c], 0.f)) + EPSF;
            unsigned long long enc = ((unsigned long long)__float_as_uint(dist) << 32);
            if (ljv[c] == la && jg != gi) {
                unsigned long long cnd = enc | (0xFFFFFFFFu - (unsigned)jg);
                if (cnd > bp) bp = cnd;
            }
            if (ljv[c] != la) {
                unsigned long long cnd = enc | (unsigned)jg;
                if (cnd < bn) bn = cnd;
            }
        }
        // reduce across the 8 tx lanes of this ty group
#pragma unroll
        for (int off = 4; off; off >>= 1) {
            unsigned long long o = __shfl_down_sync(0xffffffffu, bp, off, 8);
            if (o > bp) bp = o;
            o = __shfl_down_sync(0xffffffffu, bn, off, 8);
            if (o < bn) bn = o;
        }
        if (tx == 0) {
            if (bp) atomicMax(&g_posbest[gi], bp);        // 0 = identity
            if (bn != ~0ull) atomicMax(&g_negbest[gi], ~bn);
        }
    }
}

// ---------------------------------------------------------------------------
// K2: read final candidates, dist_unc at selected pairs, loss, last-block
//     finish. grid 128 x 4 anchors, 256 threads.  [round-12 proven config]
// ---------------------------------------------------------------------------
__global__ __launch_bounds__(256) void k_finalize(const float* __restrict__ E,
                                                  const float* __restrict__ U,
                                                  float* __restrict__ out) {
    const int t = threadIdx.x;
    const int bid = blockIdx.x;
    const int i0 = bid * 4;
    const int w = t >> 5, lane = t & 31;
    const float4* E4 = (const float4*)E;
    const float4* U4 = (const float4*)U;

    __shared__ float s_d[8];
    __shared__ int   s_v[8];
    __shared__ float s_w[8];
    __shared__ float s_us[4];
    __shared__ float s_al[4], s_av[4];
    __shared__ int   s_islast;
    __shared__ float s_red[12];

    const int a = w >> 1, side = w & 1;
    const int ia = i0 + a;

    // prefetch anchor rows (independent of candidates)
    float4 ua = U4[ia * 64 + 2 * lane];
    float4 ub = U4[ia * 64 + 2 * lane + 1];
    float4 ea = E4[ia * 64 + 2 * lane];
    float4 eb = E4[ia * 64 + 2 * lane + 1];

    // candidate (lane 0 loads, broadcast)
    unsigned long long praw = 0ull;
    if (lane == 0) praw = side ? g_negbest[ia] : g_posbest[ia];
    praw = __shfl_sync(0xffffffffu, praw, 0);
    const bool have = (praw != 0ull);
    const unsigned long long p = side ? ~praw : praw;
    const float dval = __uint_as_float((uint32_t)(p >> 32));
    const int jx = have ? (side ? (int)(uint32_t)p
                                : (int)(0xFFFFFFFFu - (uint32_t)p))
                        : 0;

    // clip u (NaN -> 1e-6 via fmaxf semantics, Inf -> 1)
    ua.x = fminf(fmaxf(ua.x, 1e-6f), 1.f); ua.y = fminf(fmaxf(ua.y, 1e-6f), 1.f);
    ua.z = fminf(fmaxf(ua.z, 1e-6f), 1.f); ua.w = fminf(fmaxf(ua.w, 1e-6f), 1.f);
    ub.x = fminf(fmaxf(ub.x, 1e-6f), 1.f); ub.y = fminf(fmaxf(ub.y, 1e-6f), 1.f);
    ub.z = fminf(fmaxf(ub.z, 1e-6f), 1.f); ub.w = fminf(fmaxf(ub.w, 1e-6f), 1.f);
    float us = ((ua.x + ua.y) + (ua.z + ua.w)) + ((ub.x + ub.y) + (ub.z + ub.w));

    // W = sum_d u_ia^2 (e_ia - e_jx)^2
    {
        float4 ja = E4[jx * 64 + 2 * lane];
        float4 jb = E4[jx * 64 + 2 * lane + 1];
        float W = 0.f, df;
        df = ea.x - ja.x; W = fmaf(ua.x * ua.x, df * df, W);
        df = ea.y - ja.y; W = fmaf(ua.y * ua.y, df * df, W);
        df = ea.z - ja.z; W = fmaf(ua.z * ua.z, df * df, W);
        df = ea.w - ja.w; W = fmaf(ua.w * ua.w, df * df, W);
        df = eb.x - jb.x; W = fmaf(ub.x * ub.x, df * df, W);
        df = eb.y - jb.y; W = fmaf(ub.y * ub.y, df * df, W);
        df = eb.z - jb.z; W = fmaf(ub.z * ub.z, df * df, W);
        df = eb.w - jb.w; W = fmaf(ub.w * ub.w, df * df, W);
#pragma unroll
        for (int off = 16; off; off >>= 1) {
            W  += __shfl_down_sync(0xffffffffu, W, off);
            us += __shfl_down_sync(0xffffffffu, us, off);
        }
        if (lane == 0) {
            s_w[w] = W;
            s_d[w] = dval;
            s_v[w] = have ? 1 : 0;
            if (side == 0) s_us[a] = us;
        }
    }
    __syncthreads();

    // per-anchor loss
    if (t < 4) {
        const int q = t;
        float dp = s_d[2 * q], dn = s_d[2 * q + 1];
        bool valid = s_v[2 * q] && s_v[2 * q + 1];
        float wp = s_w[2 * q], wn = s_w[2 * q + 1];
        float up2 = wp / (dp * dp) + EPSF;
        float un2 = wn / (dn * dn) + EPSF;
        float sig = sqrtf(up2 + un2 + EPSF);
        float me = MARGINF + UWF * sig;
        float z = (dp - dn + me) / sig;
        float sp = fmaxf(z, 0.f) + log1pf(expf(-fabsf(z)));
        s_al[q] = valid ? sig * sp : 0.f;
        s_av[q] = valid ? 1.f : 0.f;
    }
    __syncthreads();

    if (t == 0) {
        g_bl[bid] = (s_al[0] + s_al[1]) + (s_al[2] + s_al[3]);
        g_bv[bid] = (s_av[0] + s_av[1]) + (s_av[2] + s_av[3]);
        g_bu[bid] = (s_us[0] + s_us[1]) + (s_us[2] + s_us[3]);
        __threadfence();
        s_islast = (atomicInc(&g_ctr, 127) == 127) ? 1 : 0;
    }
    __syncthreads();

    if (s_islast) {
        __threadfence();
        float l = 0.f, v = 0.f, u = 0.f;
        if (t < 128) {
            l = *(volatile float*)&g_bl[t];
            v = *(volatile float*)&g_bv[t];
            u = *(volatile float*)&g_bu[t];
        }
#pragma unroll
        for (int off = 16; off; off >>= 1) {
            l += __shfl_down_sync(0xffffffffu, l, off);
            v += __shfl_down_sync(0xffffffffu, v, off);
            u += __shfl_down_sync(0xffffffffu, u, off);
        }
        if (lane == 0 && w < 4) {
            s_red[w] = l; s_red[4 + w] = v; s_red[8 + w] = u;
        }
        __syncthreads();
        if (t == 0) {
            float L = (s_red[0] + s_red[1]) + (s_red[2] + s_red[3]);
            float V = (s_red[4] + s_red[5]) + (s_red[6] + s_red[7]);
            float Uu = (s_red[8] + s_red[9]) + (s_red[10] + s_red[11]);
            float total = L / fmaxf(V, 1.0f) + UWF * (Uu / (float)(BSZ * DSZ));
            if (isnan(total) || isinf(total)) total = 0.f;
            out[0] = total;
        }
    }
}

// ---------------------------------------------------------------------------
extern "C" void kernel_launch(void* const* d_in, const int* in_sizes, int n_in,
                              void* d_out, int out_size) {
    const float* E = (const float*)d_in[0];
    const float* U = (const float*)d_in[1];
    const int*   L = (const int*)d_in[2];
    float* out = (float*)d_out;

    k_dist_mine<<<dim3(16, 8), 256>>>(E, L);
    k_finalize<<<128, 256>>>(E, U, out);
}

// round 16
// speedup vs baseline: 1.1366x; 1.0493x over previous
#include <cuda_runtime.h>
#include <math.h>
#include <stdint.h>

#define BSZ 512
#define DSZ 256
#define EPSF 1e-8f
#define MARGINF 0.3f
#define UWF 0.05f

// ---------------------------------------------------------------------------
// scratch (__device__ globals; no cudaMalloc allowed)
// Zero is the identity for both atomics (neg side stored complemented) and
// integer max is idempotent/order-independent -> graph-replay deterministic.
// ---------------------------------------------------------------------------
__device__ unsigned long long g_posbest[BSZ];    // packed max (0 = none)
__device__ unsigned long long g_negbest[BSZ];    // ~packed min (0 = none)
__device__ float g_bl[128], g_bv[128], g_bu[128];
__device__ unsigned int g_ctr = 0;               // wraps via atomicInc(.,127)

// packed f32x2 FMA: d = a*b + d (lane-wise IEEE fma)
#define FMA2(d, a, b) \
    asm("fma.rn.f32x2 %0, %1, %2, %0;" : "+l"(d) : "l"(a), "l"(b))

__device__ __forceinline__ uint32_t smem_u32(const void* p) {
    uint32_t r;
    asm("{ .reg .u64 t; cvta.to.shared.u64 t, %1; cvt.u32.u64 %0, t; }"
        : "=r"(r) : "l"(p));
    return r;
}

// ---------------------------------------------------------------------------
// K1: 64(i) x 32(j) distance tiles, 256 threads (8 warps/SM = 2/SMSP),
//     thread-tile 2x4, NARROW-B loads (v4.b32 + register dup), 32-d chunks.
//     grid (16 j-tiles, 8 i-rows) = 128 blocks.  [round-12 champion]
// ---------------------------------------------------------------------------
__global__ __launch_bounds__(256) void k_dist_mine(const float* __restrict__ E,
                                                   const int*   __restrict__ L) {
    __shared__ __align__(16) float As[32][68];   // [d_local][i_local] (64+pad)
    __shared__ __align__(16) float Bs[32][36];   // [d_local][j_local] (32+pad)
    __shared__ float sni[64], snj[32];
    __shared__ int   sli[64], slj[32];

    const int t = threadIdx.x;
    const int i0 = blockIdx.y * 64;
    const int j0 = blockIdx.x * 32;
    const int tx = t & 7;         // j-quad (0..7)
    const int ty = t >> 3;        // i-pair (0..31)
    const float4* E4 = (const float4*)E;

    // loader lanes
    const int ar = t >> 2, aq = t & 3;   // A: 64 rows x 4 threads, 2 f4 each
    const int br = t >> 3, bq = t & 7;   // B: 32 rows x 8 threads, 1 f4 each

    if (t < 64) sli[t] = L[i0 + t];
    if (t < 32) slj[t] = L[j0 + t];

    // 4 packed accumulators: acc[c] = i rows (2ty, 2ty+1) x j col (4tx+c)
    uint64_t acc[4] = {0, 0, 0, 0};
    float nA = 0.f, nB = 0.f;

    const uint32_t as_base = smem_u32(&As[0][2 * ty]);
    const uint32_t bs_base = smem_u32(&Bs[0][4 * tx]);

    float4 pa[2], pb;
#pragma unroll
    for (int k = 0; k < 2; k++) pa[k] = E4[(i0 + ar) * 64 + aq + 4 * k];
    pb = E4[(j0 + br) * 64 + bq];

#pragma unroll 1
    for (int ch = 0; ch < 8; ch++) {
        // inline norm accumulation from prefetched registers
#pragma unroll
        for (int k = 0; k < 2; k++) {
            nA = fmaf(pa[k].x, pa[k].x, nA); nA = fmaf(pa[k].y, pa[k].y, nA);
            nA = fmaf(pa[k].z, pa[k].z, nA); nA = fmaf(pa[k].w, pa[k].w, nA);
        }
        nB = fmaf(pb.x, pb.x, nB); nB = fmaf(pb.y, pb.y, nB);
        nB = fmaf(pb.z, pb.z, nB); nB = fmaf(pb.w, pb.w, nB);

        // stage (transpose) into smem
#pragma unroll
        for (int k = 0; k < 2; k++) {
            int q = aq + 4 * k;
            As[q * 4 + 0][ar] = pa[k].x;
            As[q * 4 + 1][ar] = pa[k].y;
            As[q * 4 + 2][ar] = pa[k].z;
            As[q * 4 + 3][ar] = pa[k].w;
        }
        Bs[bq * 4 + 0][br] = pb.x;
        Bs[bq * 4 + 1][br] = pb.y;
        Bs[bq * 4 + 2][br] = pb.z;
        Bs[bq * 4 + 3][br] = pb.w;
        __syncthreads();

        if (ch < 7) {
#pragma unroll
            for (int k = 0; k < 2; k++)
                pa[k] = E4[(i0 + ar) * 64 + (ch + 1) * 8 + aq + 4 * k];
            pb = E4[(j0 + br) * 64 + (ch + 1) * 8 + bq];
        }

#pragma unroll
        for (int d = 0; d < 32; d++) {
            uint64_t a01;
            asm("ld.shared.b64 %0, [%1];"
                : "=l"(a01) : "r"(as_base + d * (68 * 4)));
            uint32_t b0, b1, b2, b3;
            asm("ld.shared.v4.b32 {%0, %1, %2, %3}, [%4];"
                : "=r"(b0), "=r"(b1), "=r"(b2), "=r"(b3)
                : "r"(bs_base + d * (36 * 4)));
            uint64_t bb0, bb1, bb2, bb3;
            asm("mov.b64 %0, {%1, %1};" : "=l"(bb0) : "r"(b0));
            asm("mov.b64 %0, {%1, %1};" : "=l"(bb1) : "r"(b1));
            asm("mov.b64 %0, {%1, %1};" : "=l"(bb2) : "r"(b2));
            asm("mov.b64 %0, {%1, %1};" : "=l"(bb3) : "r"(b3));
            FMA2(acc[0], a01, bb0);
            FMA2(acc[1], a01, bb1);
            FMA2(acc[2], a01, bb2);
            FMA2(acc[3], a01, bb3);
        }
        __syncthreads();
    }

    // publish row norms
    nA += __shfl_xor_sync(0xffffffffu, nA, 1);
    nA += __shfl_xor_sync(0xffffffffu, nA, 2);
    if (aq == 0) sni[ar] = nA;
    nB += __shfl_xor_sync(0xffffffffu, nB, 1);
    nB += __shfl_xor_sync(0xffffffffu, nB, 2);
    nB += __shfl_xor_sync(0xffffffffu, nB, 4);
    if (bq == 0) snj[br] = nB;
    __syncthreads();

    // unpack dots: dt[r][c], r = i within pair, c = j within quad
    float dt[2][4];
#pragma unroll
    for (int c = 0; c < 4; c++) {
        uint32_t lo, hi;
        asm("mov.b64 {%0, %1}, %2;" : "=r"(lo), "=r"(hi) : "l"(acc[c]));
        dt[0][c] = __uint_as_float(lo);
        dt[1][c] = __uint_as_float(hi);
    }

    float njv[4]; int ljv[4];
#pragma unroll
    for (int c = 0; c < 4; c++) { njv[c] = snj[4 * tx + c]; ljv[c] = slj[4 * tx + c]; }

#pragma unroll
    for (int r = 0; r < 2; r++) {
        const int gi = i0 + 2 * ty + r;
        const int la = sli[2 * ty + r];
        const float nir = sni[2 * ty + r];

        unsigned long long bp = 0ull;   // pos: max dist, same label, j!=i; tie -> low j
        unsigned long long bn = ~0ull;  // neg: min dist, diff label; tie -> low j
#pragma unroll
        for (int c = 0; c < 4; c++) {
            const int jg = j0 + 4 * tx + c;
            float dist = sqrtf(fmaxf(nir + njv[c] - 2.f * dt[r][c], 0.f)) + EPSF;
            unsigned long long enc = ((unsigned long long)__float_as_uint(dist) << 32);
            if (ljv[c] == la && jg != gi) {
                unsigned long long cnd = enc | (0xFFFFFFFFu - (unsigned)jg);
                if (cnd > bp) bp = cnd;
            }
            if (ljv[c] != la) {
                unsigned long long cnd = enc | (unsigned)jg;
                if (cnd < bn) bn = cnd;
            }
        }
        // reduce across the 8 tx lanes of this ty group
#pragma unroll
        for (int off = 4; off; off >>= 1) {
            unsigned long long o = __shfl_down_sync(0xffffffffu, bp, off, 8);
            if (o > bp) bp = o;
            o = __shfl_down_sync(0xffffffffu, bn, off, 8);
            if (o < bn) bn = o;
        }
        if (tx == 0) {
            atomicMax(&g_posbest[gi], bp);   // idempotent combine (0 = identity)
            atomicMax(&g_negbest[gi], ~bn);
        }
    }
}

// ---------------------------------------------------------------------------
// K2: read final candidates, dist_unc at selected pairs, loss, last-block
//     finish. grid 128 x 4 anchors, 256 threads. Warp w = (anchor w/2, side w&1).
//     [round-10/12 proven config]
// ---------------------------------------------------------------------------
__global__ __launch_bounds__(256) void k_finalize(const float* __restrict__ E,
                                                  const float* __restrict__ U,
                                                  float* __restrict__ out) {
    const int t = threadIdx.x;
    const int bid = blockIdx.x;
    const int i0 = bid * 4;
    const int w = t >> 5, lane = t & 31;
    const float4* E4 = (const float4*)E;
    const float4* U4 = (const float4*)U;

    __shared__ float s_d[8];
    __shared__ int   s_v[8];
    __shared__ float s_w[8];
    __shared__ float s_us[4];
    __shared__ float s_al[4], s_av[4];
    __shared__ int   s_islast;
    __shared__ float s_red[12];

    const int a = w >> 1, side = w & 1;
    const int ia = i0 + a;

    // prefetch anchor rows (independent of candidates -> overlaps candidate LDG)
    float4 ua = U4[ia * 64 + 2 * lane];
    float4 ub = U4[ia * 64 + 2 * lane + 1];
    float4 ea = E4[ia * 64 + 2 * lane];
    float4 eb = E4[ia * 64 + 2 * lane + 1];

    // candidate (lane 0 loads, broadcast)
    unsigned long long praw = 0ull;
    if (lane == 0) praw = side ? g_negbest[ia] : g_posbest[ia];
    praw = __shfl_sync(0xffffffffu, praw, 0);
    const bool have = (praw != 0ull);
    const unsigned long long p = side ? ~praw : praw;
    const float dval = __uint_as_float((uint32_t)(p >> 32));
    const int jx = have ? (side ? (int)(uint32_t)p
                                : (int)(0xFFFFFFFFu - (uint32_t)p))
                        : 0;

    // clip u (NaN -> 1e-6 via fmaxf semantics, Inf -> 1)
    ua.x = fminf(fmaxf(ua.x, 1e-6f), 1.f); ua.y = fminf(fmaxf(ua.y, 1e-6f), 1.f);
    ua.z = fminf(fmaxf(ua.z, 1e-6f), 1.f); ua.w = fminf(fmaxf(ua.w, 1e-6f), 1.f);
    ub.x = fminf(fmaxf(ub.x, 1e-6f), 1.f); ub.y = fminf(fmaxf(ub.y, 1e-6f), 1.f);
    ub.z = fminf(fmaxf(ub.z, 1e-6f), 1.f); ub.w = fminf(fmaxf(ub.w, 1e-6f), 1.f);
    float us = ((ua.x + ua.y) + (ua.z + ua.w)) + ((ub.x + ub.y) + (ub.z + ub.w));

    // W = sum_d u_ia^2 (e_ia - e_jx)^2
    {
        float4 ja = E4[jx * 64 + 2 * lane];
        float4 jb = E4[jx * 64 + 2 * lane + 1];
        float W = 0.f, df;
        df = ea.x - ja.x; W = fmaf(ua.x * ua.x, df * df, W);
        df = ea.y - ja.y; W = fmaf(ua.y * ua.y, df * df, W);
        df = ea.z - ja.z; W = fmaf(ua.z * ua.z, df * df, W);
        df = ea.w - ja.w; W = fmaf(ua.w * ua.w, df * df, W);
        df = eb.x - jb.x; W = fmaf(ub.x * ub.x, df * df, W);
        df = eb.y - jb.y; W = fmaf(ub.y * ub.y, df * df, W);
        df = eb.z - jb.z; W = fmaf(ub.z * ub.z, df * df, W);
        df = eb.w - jb.w; W = fmaf(ub.w * ub.w, df * df, W);
#pragma unroll
        for (int off = 16; off; off >>= 1) {
            W  += __shfl_down_sync(0xffffffffu, W, off);
            us += __shfl_down_sync(0xffffffffu, us, off);
        }
        if (lane == 0) {
            s_w[w] = W;
            s_d[w] = dval;
            s_v[w] = have ? 1 : 0;
            if (side == 0) s_us[a] = us;
        }
    }
    __syncthreads();

    // per-anchor loss
    if (t < 4) {
        const int q = t;
        float dp = s_d[2 * q], dn = s_d[2 * q + 1];
        bool valid = s_v[2 * q] && s_v[2 * q + 1];
        float wp = s_w[2 * q], wn = s_w[2 * q + 1];
        float up2 = wp / (dp * dp) + EPSF;
        float un2 = wn / (dn * dn) + EPSF;
        float sig = sqrtf(up2 + un2 + EPSF);
        float me = MARGINF + UWF * sig;
        float z = (dp - dn + me) / sig;
        float sp = fmaxf(z, 0.f) + log1pf(expf(-fabsf(z)));
        s_al[q] = valid ? sig * sp : 0.f;
        s_av[q] = valid ? 1.f : 0.f;
    }
    __syncthreads();

    if (t == 0) {
        g_bl[bid] = (s_al[0] + s_al[1]) + (s_al[2] + s_al[3]);
        g_bv[bid] = (s_av[0] + s_av[1]) + (s_av[2] + s_av[3]);
        g_bu[bid] = (s_us[0] + s_us[1]) + (s_us[2] + s_us[3]);
        __threadfence();
        s_islast = (atomicInc(&g_ctr, 127) == 127) ? 1 : 0;
    }
    __syncthreads();

    if (s_islast) {
        __threadfence();
        float l = 0.f, v = 0.f, u = 0.f;
        if (t < 128) {
            l = *(volatile float*)&g_bl[t];
            v = *(volatile float*)&g_bv[t];
            u = *(volatile float*)&g_bu[t];
        }
#pragma unroll
        for (int off = 16; off; off >>= 1) {
            l += __shfl_down_sync(0xffffffffu, l, off);
            v += __shfl_down_sync(0xffffffffu, v, off);
            u += __shfl_down_sync(0xffffffffu, u, off);
        }
        if (lane == 0 && w < 4) {
            s_red[w] = l; s_red[4 + w] = v; s_red[8 + w] = u;
        }
        __syncthreads();
        if (t == 0) {
            float L = (s_red[0] + s_red[1]) + (s_red[2] + s_red[3]);
            float V = (s_red[4] + s_red[5]) + (s_red[6] + s_red[7]);
            float Uu = (s_red[8] + s_red[9]) + (s_red[10] + s_red[11]);
            float total = L / fmaxf(V, 1.0f) + UWF * (Uu / (float)(BSZ * DSZ));
            if (isnan(total) || isinf(total)) total = 0.f;
            out[0] = total;
        }
    }
}

// ---------------------------------------------------------------------------
extern "C" void kernel_launch(void* const* d_in, const int* in_sizes, int n_in,
                              void* d_out, int out_size) {
    const float* E = (const float*)d_in[0];
    const float* U = (const float*)d_in[1];
    const int*   L = (const int*)d_in[2];
    float* out = (float*)d_out;

    k_dist_mine<<<dim3(16, 8), 256>>>(E, L);
    k_finalize<<<128, 256>>>(E, U, out);
}